// round 2
// baseline (speedup 1.0000x reference)
#include <cuda_runtime.h>
#include <math.h>

// ---------------- problem constants ----------------
#define CC     10
#define NCLUST 11            // C+1
#define NSEG   88            // B * (C+1)
#define BATCH  8
#define NPB    16384         // tokens per batch
#define MTOT   131072        // B*N
#define IDIM   512
#define EMBD   8
#define DDIM   256

// ---------------- scratch (static device globals; no dynamic alloc) ----------------
__device__ float g_x[(size_t)MTOT * IDIM];     // fused features, 256 MiB
__device__ float g_A[MTOT];                    // intra attention logits
__device__ float g_ex[MTOT];                   // exp(A - segmax)
__device__ float g_segmax[NSEG];
__device__ float g_segsum[NSEG];
__device__ int   g_counts[NSEG];
__device__ float g_cfraw[NSEG * IDIM];         // weighted segment sums
__device__ float g_cfeat[NSEG * IDIM];         // after W_intra + relu
__device__ float g_A2[NSEG];                   // inter attention logits

// ---------------- helpers ----------------
__device__ __forceinline__ void atomicMaxFloat(float* addr, float val) {
    int* ia = (int*)addr;
    int old = *ia;
    while (__int_as_float(old) < val) {
        int assumed = old;
        old = atomicCAS(ia, assumed, __float_as_int(val));
        if (old == assumed) break;
    }
}

__device__ __forceinline__ float sigmoidf_(float v) {
    return 1.0f / (1.0f + expf(-v));
}

// ---------------- kernel 0: init segment stats ----------------
__global__ void init_kernel() {
    int tid = threadIdx.x;
    if (tid < NSEG) {
        g_segmax[tid] = -1e30f;
        g_segsum[tid] = 0.0f;
        g_counts[tid] = 0;
    }
    for (int i = tid; i < NSEG * IDIM; i += blockDim.x)
        g_cfraw[i] = 0.0f;
}

// ---------------- kernel 1: x = relu([h | emb[cid]] @ W_fuse + b_fuse) ----------------
// GEMM M=131072, N=512, K=520 (512 via tiles + 8 emb columns as epilogue)
// block = 128x64 tile, BK=16, 256 threads, 8x4 microtile
__global__ __launch_bounds__(256) void fuse_kernel(
    const float* __restrict__ h, const int* __restrict__ cids,
    const float* __restrict__ emb, const float* __restrict__ Wf,
    const float* __restrict__ bf)
{
    __shared__ float As[128][16];
    __shared__ float Bs[16][64];
    const int tid = threadIdx.x;
    const int m0  = blockIdx.y * 128;
    const int n0  = blockIdx.x * 64;
    const int tm  = (tid >> 4) * 8;
    const int tn  = (tid & 15) * 4;

    float acc[8][4];
#pragma unroll
    for (int r = 0; r < 8; r++)
#pragma unroll
        for (int c = 0; c < 4; c++) acc[r][c] = 0.0f;

    for (int kt = 0; kt < 32; kt++) {
        const int k0 = kt * 16;
#pragma unroll
        for (int i = 0; i < 8; i++) {
            int idx = i * 256 + tid;
            int k = idx & 15, row = idx >> 4;
            As[row][k] = h[(size_t)(m0 + row) * IDIM + k0 + k];
        }
#pragma unroll
        for (int i = 0; i < 4; i++) {
            int idx = i * 256 + tid;
            int n = idx & 63, kk = idx >> 6;
            Bs[kk][n] = Wf[(size_t)(k0 + kk) * IDIM + n0 + n];
        }
        __syncthreads();
#pragma unroll
        for (int k = 0; k < 16; k++) {
            float4 b4 = *(const float4*)&Bs[k][tn];
#pragma unroll
            for (int r = 0; r < 8; r++) {
                float av = As[tm + r][k];
                acc[r][0] += av * b4.x;
                acc[r][1] += av * b4.y;
                acc[r][2] += av * b4.z;
                acc[r][3] += av * b4.w;
            }
        }
        __syncthreads();
    }

    // embedding epilogue: += emb[cid[m]] @ W_fuse[512:520, n]
#pragma unroll
    for (int r = 0; r < 8; r++) {
        int m = m0 + tm + r;
        int cid = cids[m];
        cid = min(max(cid, 0), CC);
        const float* ev = emb + cid * EMBD;
#pragma unroll
        for (int e = 0; e < EMBD; e++) {
            float evv = ev[e];
            const float* wr = Wf + (size_t)(IDIM + e) * IDIM + n0 + tn;
            acc[r][0] += evv * wr[0];
            acc[r][1] += evv * wr[1];
            acc[r][2] += evv * wr[2];
            acc[r][3] += evv * wr[3];
        }
    }

    const float bv0 = bf[n0 + tn + 0];
    const float bv1 = bf[n0 + tn + 1];
    const float bv2 = bf[n0 + tn + 2];
    const float bv3 = bf[n0 + tn + 3];
#pragma unroll
    for (int r = 0; r < 8; r++) {
        float4 o;
        o.x = fmaxf(acc[r][0] + bv0, 0.0f);
        o.y = fmaxf(acc[r][1] + bv1, 0.0f);
        o.z = fmaxf(acc[r][2] + bv2, 0.0f);
        o.w = fmaxf(acc[r][3] + bv3, 0.0f);
        *(float4*)&g_x[(size_t)(m0 + tm + r) * IDIM + n0 + tn] = o;
    }
}

// ---------------- kernel 2: A[m] = sum_d tanh(x@Wa1+ba1)*sigm(x@Wb1+bb1)*Wc1[d] + bc1 ----------------
// block: 128 rows; d processed in 4 tiles of 64; BK=16; 256 threads, 8 rows x 4 d microtile (x2 matrices)
// deterministic reduction: per-(row-group, d-lane) partials in shared, tree-reduce at the end
__global__ __launch_bounds__(256) void attn1_kernel(
    const float* __restrict__ Wa1, const float* __restrict__ ba1,
    const float* __restrict__ Wb1, const float* __restrict__ bb1,
    const float* __restrict__ Wc1, const float* __restrict__ bc1)
{
    __shared__ float Xs[128][16];
    __shared__ float Was[16][64];
    __shared__ float Wbs[16][64];
    __shared__ float sP[16][128 + 1];   // [d-lane][row] partials (+1 pad vs bank conflicts)
    const int tid = threadIdx.x;
    const int m0  = blockIdx.x * 128;
    const int tm  = (tid >> 4) * 8;     // row group base (16 groups of 8)
    const int lane = tid & 15;          // d lane
    const int tc  = lane * 4;

    float rowsum[8];
#pragma unroll
    for (int r = 0; r < 8; r++) rowsum[r] = 0.0f;

    for (int dt = 0; dt < 4; dt++) {
        float a[8][4], g[8][4];
#pragma unroll
        for (int r = 0; r < 8; r++)
#pragma unroll
            for (int c = 0; c < 4; c++) { a[r][c] = 0.0f; g[r][c] = 0.0f; }

        for (int kt = 0; kt < 32; kt++) {
            const int k0 = kt * 16;
#pragma unroll
            for (int i = 0; i < 8; i++) {
                int idx = i * 256 + tid;
                int k = idx & 15, row = idx >> 4;
                Xs[row][k] = g_x[(size_t)(m0 + row) * IDIM + k0 + k];
            }
#pragma unroll
            for (int i = 0; i < 4; i++) {
                int idx = i * 256 + tid;
                int d = idx & 63, kk = idx >> 6;
                Was[kk][d] = Wa1[(size_t)(k0 + kk) * DDIM + dt * 64 + d];
                Wbs[kk][d] = Wb1[(size_t)(k0 + kk) * DDIM + dt * 64 + d];
            }
            __syncthreads();
#pragma unroll
            for (int k = 0; k < 16; k++) {
                float4 wa = *(const float4*)&Was[k][tc];
                float4 wb = *(const float4*)&Wbs[k][tc];
#pragma unroll
                for (int r = 0; r < 8; r++) {
                    float xv = Xs[tm + r][k];
                    a[r][0] += xv * wa.x; a[r][1] += xv * wa.y;
                    a[r][2] += xv * wa.z; a[r][3] += xv * wa.w;
                    g[r][0] += xv * wb.x; g[r][1] += xv * wb.y;
                    g[r][2] += xv * wb.z; g[r][3] += xv * wb.w;
                }
            }
            __syncthreads();
        }

        // gated pointwise + partial reduction over this d-tile (per-thread, deterministic)
        float4 bav = *(const float4*)&ba1[dt * 64 + tc];
        float4 bbv = *(const float4*)&bb1[dt * 64 + tc];
        float4 wcv = *(const float4*)&Wc1[dt * 64 + tc];
#pragma unroll
        for (int r = 0; r < 8; r++) {
            float s;
            s  = tanhf(a[r][0] + bav.x) * sigmoidf_(g[r][0] + bbv.x) * wcv.x;
            s += tanhf(a[r][1] + bav.y) * sigmoidf_(g[r][1] + bbv.y) * wcv.y;
            s += tanhf(a[r][2] + bav.z) * sigmoidf_(g[r][2] + bbv.z) * wcv.z;
            s += tanhf(a[r][3] + bav.w) * sigmoidf_(g[r][3] + bbv.w) * wcv.w;
            rowsum[r] += s;
        }
    }

    // deterministic cross-lane reduction: sP[lane][row]
#pragma unroll
    for (int r = 0; r < 8; r++) sP[lane][tm + r] = rowsum[r];
    __syncthreads();
    // 128 threads each own one row; sum 16 lanes in fixed order
    if (tid < 128) {
        float s = 0.0f;
#pragma unroll
        for (int l = 0; l < 16; l++) s += sP[l][tid];
        g_A[m0 + tid] = s + bc1[0];
    }
}

// ---------------- kernel 3: segment max ----------------
__global__ void segmax_kernel(const int* __restrict__ cids) {
    __shared__ float smax[NSEG];
    const int tid = threadIdx.x;
    if (tid < NSEG) smax[tid] = -1e30f;
    __syncthreads();
    for (int m = blockIdx.x * blockDim.x + tid; m < MTOT; m += gridDim.x * blockDim.x) {
        int cid = cids[m];
        cid = min(max(cid, 0), CC);
        int seg = (m >> 14) * NCLUST + cid;
        atomicMaxFloat(&smax[seg], g_A[m]);
    }
    __syncthreads();
    if (tid < NSEG) atomicMaxFloat(&g_segmax[tid], smax[tid]);
}

// ---------------- kernel 4: ex = exp(A - segmax), segment sum + counts ----------------
__global__ void segsum_kernel(const int* __restrict__ cids) {
    __shared__ float ssum[NSEG];
    __shared__ int   scnt[NSEG];
    const int tid = threadIdx.x;
    if (tid < NSEG) { ssum[tid] = 0.0f; scnt[tid] = 0; }
    __syncthreads();
    for (int m = blockIdx.x * blockDim.x + tid; m < MTOT; m += gridDim.x * blockDim.x) {
        int cid = cids[m];
        cid = min(max(cid, 0), CC);
        int seg = (m >> 14) * NCLUST + cid;
        float ex = expf(g_A[m] - g_segmax[seg]);
        g_ex[m] = ex;
        atomicAdd(&ssum[seg], ex);
        atomicAdd(&scnt[seg], 1);
    }
    __syncthreads();
    if (tid < NSEG) {
        atomicAdd(&g_segsum[tid], ssum[tid]);
        atomicAdd(&g_counts[tid], scnt[tid]);
    }
}

// ---------------- kernel 5: cfraw[seg] += w * x[m]   (w = ex/denom) ----------------
// each block: 256 consecutive rows of one batch; shared 11x512 partials; rows processed
// sequentially so each column is owned by exactly one thread (race-free)
__global__ __launch_bounds__(256) void cfeat_kernel(const int* __restrict__ cids) {
    __shared__ float sh[NCLUST][IDIM];
    const int tid = threadIdx.x;
    const int b     = blockIdx.x >> 6;   // 64 chunks per batch
    const int chunk = blockIdx.x & 63;
    for (int i = tid; i < NCLUST * IDIM; i += 256) ((float*)sh)[i] = 0.0f;
    __syncthreads();
    const int mbase = b * NPB + chunk * 256;
    for (int r = 0; r < 256; r++) {
        int m = mbase + r;
        int cid = cids[m];
        cid = min(max(cid, 0), CC);
        float w = g_ex[m] / g_segsum[b * NCLUST + cid];
        const float* xr = &g_x[(size_t)m * IDIM];
        sh[cid][tid]       += w * xr[tid];
        sh[cid][tid + 256] += w * xr[tid + 256];
    }
    __syncthreads();
    for (int c = 0; c < NCLUST; c++) {
        atomicAdd(&g_cfraw[(b * NCLUST + c) * IDIM + tid],       sh[c][tid]);
        atomicAdd(&g_cfraw[(b * NCLUST + c) * IDIM + tid + 256], sh[c][tid + 256]);
    }
}

// ---------------- kernel 6: cfeat = relu(cfraw @ W_intra + b_intra)  [88,512] ----------------
__global__ __launch_bounds__(256) void intra_kernel(
    const float* __restrict__ Wi, const float* __restrict__ bi)
{
    __shared__ float xr[IDIM];
    const int s = blockIdx.x, tid = threadIdx.x;
    xr[tid]       = g_cfraw[s * IDIM + tid];
    xr[tid + 256] = g_cfraw[s * IDIM + tid + 256];
    __syncthreads();
#pragma unroll
    for (int jj = 0; jj < 2; jj++) {
        int j = tid + jj * 256;
        float acc = bi[j];
        for (int k = 0; k < IDIM; k++) acc += xr[k] * Wi[(size_t)k * IDIM + j];
        g_cfeat[s * IDIM + j] = fmaxf(acc, 0.0f);
    }
}

// ---------------- kernel 7: inter-cluster gated logits A2[88] ----------------
__global__ __launch_bounds__(256) void attn2_kernel(
    const float* __restrict__ Wa2, const float* __restrict__ ba2,
    const float* __restrict__ Wb2, const float* __restrict__ bb2,
    const float* __restrict__ Wc2, const float* __restrict__ bc2)
{
    __shared__ float xr[IDIM];
    __shared__ float red[256];
    const int s = blockIdx.x, tid = threadIdx.x;
    xr[tid]       = g_cfeat[s * IDIM + tid];
    xr[tid + 256] = g_cfeat[s * IDIM + tid + 256];
    __syncthreads();
    float aa = ba2[tid], bb = bb2[tid];
    for (int k = 0; k < IDIM; k++) {
        float xv = xr[k];
        aa += xv * Wa2[(size_t)k * DDIM + tid];
        bb += xv * Wb2[(size_t)k * DDIM + tid];
    }
    red[tid] = tanhf(aa) * sigmoidf_(bb) * Wc2[tid];
    __syncthreads();
    for (int off = 128; off > 0; off >>= 1) {
        if (tid < off) red[tid] += red[tid + off];
        __syncthreads();
    }
    if (tid == 0)
        g_A2[s] = (g_counts[s] > 0) ? (red[0] + bc2[0]) : -1e30f;
}

// ---------------- kernel 8: per-batch softmax, pooling, classifier ----------------
__global__ __launch_bounds__(256) void final_kernel(
    const float* __restrict__ Wint, const float* __restrict__ bint,
    const float* __restrict__ Wcls, const float* __restrict__ bcls,
    float* __restrict__ out)
{
    __shared__ float sWs[NCLUST];
    __shared__ float sl[IDIM];
    __shared__ float st2[256];
    __shared__ float red[256];
    const int b = blockIdx.x, tid = threadIdx.x;

    if (tid == 0) {
        float mx = -1e30f;
        for (int c = 0; c < NCLUST; c++) mx = fmaxf(mx, g_A2[b * NCLUST + c]);
        float e[NCLUST]; float sum = 0.0f;
        for (int c = 0; c < NCLUST; c++) { e[c] = expf(g_A2[b * NCLUST + c] - mx); sum += e[c]; }
        for (int c = 0; c < NCLUST; c++) sWs[c] = e[c] / sum;
    }
    __syncthreads();

#pragma unroll
    for (int jj = 0; jj < 2; jj++) {
        int j = tid + jj * 256;
        float s = 0.0f;
        for (int c = 0; c < NCLUST; c++)
            s += sWs[c] * g_cfeat[(b * NCLUST + c) * IDIM + j];
        sl[j] = s;
    }
    __syncthreads();

    float acc = bint[tid];
    for (int k = 0; k < IDIM; k++) acc += sl[k] * Wint[(size_t)k * 256 + tid];
    st2[tid] = fmaxf(acc, 0.0f);
    __syncthreads();

    // out column 0
    red[tid] = st2[tid] * Wcls[tid * 2 + 0];
    __syncthreads();
    for (int off = 128; off > 0; off >>= 1) {
        if (tid < off) red[tid] += red[tid + off];
        __syncthreads();
    }
    if (tid == 0) out[b * 2 + 0] = red[0] + bcls[0];
    __syncthreads();

    // out column 1
    red[tid] = st2[tid] * Wcls[tid * 2 + 1];
    __syncthreads();
    for (int off = 128; off > 0; off >>= 1) {
        if (tid < off) red[tid] += red[tid + off];
        __syncthreads();
    }
    if (tid == 0) out[b * 2 + 1] = red[0] + bcls[1];
}

// ---------------- launch ----------------
extern "C" void kernel_launch(void* const* d_in, const int* in_sizes, int n_in,
                              void* d_out, int out_size)
{
    const float* h       = (const float*)d_in[0];
    const int*   cids    = (const int*)  d_in[1];
    const float* emb     = (const float*)d_in[2];
    const float* W_fuse  = (const float*)d_in[3];
    const float* b_fuse  = (const float*)d_in[4];
    const float* Wa1     = (const float*)d_in[5];
    const float* ba1     = (const float*)d_in[6];
    const float* Wb1     = (const float*)d_in[7];
    const float* bb1     = (const float*)d_in[8];
    const float* Wc1     = (const float*)d_in[9];
    const float* bc1     = (const float*)d_in[10];
    const float* W_intra = (const float*)d_in[11];
    const float* b_intra = (const float*)d_in[12];
    const float* Wa2     = (const float*)d_in[13];
    const float* ba2     = (const float*)d_in[14];
    const float* Wb2     = (const float*)d_in[15];
    const float* bb2     = (const float*)d_in[16];
    const float* Wc2     = (const float*)d_in[17];
    const float* bc2     = (const float*)d_in[18];
    const float* W_inter = (const float*)d_in[19];
    const float* b_inter = (const float*)d_in[20];
    const float* W_cls   = (const float*)d_in[21];
    const float* b_cls   = (const float*)d_in[22];
    float* out = (float*)d_out;

    init_kernel<<<1, 512>>>();
    fuse_kernel<<<dim3(IDIM / 64, MTOT / 128), 256>>>(h, cids, emb, W_fuse, b_fuse);
    attn1_kernel<<<MTOT / 128, 256>>>(Wa1, ba1, Wb1, bb1, Wc1, bc1);
    segmax_kernel<<<256, 256>>>(cids);
    segsum_kernel<<<256, 256>>>(cids);
    cfeat_kernel<<<BATCH * 64, 256>>>(cids);
    intra_kernel<<<NSEG, 256>>>(W_intra, b_intra);
    attn2_kernel<<<NSEG, 256>>>(Wa2, ba2, Wb2, bb2, Wc2, bc2);
    final_kernel<<<BATCH, 256>>>(W_inter, b_inter, W_cls, b_cls, out);
}

// round 3
// speedup vs baseline: 2.5302x; 2.5302x over previous
#include <cuda_runtime.h>
#include <math.h>
#include <stdint.h>

// ---------------- problem constants ----------------
#define CC     10
#define NCLUST 11            // C+1
#define NSEG   88            // B * (C+1)
#define BATCH  8
#define NPB    16384         // tokens per batch
#define MTOT   131072        // B*N
#define IDIM   512
#define EMBD   8
#define DDIM   256

// ---------------- scratch (static device globals) ----------------
__device__ float g_x[(size_t)MTOT * IDIM];     // fused features, 256 MiB
__device__ float g_A[MTOT];                    // intra attention logits (bc1 folded out: softmax-invariant)
__device__ float g_ex[MTOT];                   // exp(A - segmax)
__device__ float g_segmax[NSEG];
__device__ float g_segsum[NSEG];
__device__ int   g_counts[NSEG];
__device__ float g_cfraw[NSEG * IDIM];         // weighted segment sums
__device__ float g_cfeat[NSEG * IDIM];         // after W_intra + relu
__device__ float g_A2[NSEG];                   // inter attention logits

// ---------------- helpers ----------------
__device__ __forceinline__ void atomicMaxFloat(float* addr, float val) {
    int* ia = (int*)addr;
    int old = *ia;
    while (__int_as_float(old) < val) {
        int assumed = old;
        old = atomicCAS(ia, assumed, __float_as_int(val));
        if (old == assumed) break;
    }
}

__device__ __forceinline__ float sigmoidf_(float v) {
    return 1.0f / (1.0f + expf(-v));
}

__device__ __forceinline__ uint32_t f2tf32(float x) {
    uint32_t r;
    asm("cvt.rna.tf32.f32 %0, %1;" : "=r"(r) : "f"(x));
    return r;
}

// m16n8k8 tf32 mma, row.col, fp32 accum
__device__ __forceinline__ void mma_tf32(float* d, const uint32_t* a, const uint32_t* b) {
    asm volatile(
        "mma.sync.aligned.m16n8k8.row.col.f32.tf32.tf32.f32 "
        "{%0,%1,%2,%3}, {%4,%5,%6,%7}, {%8,%9}, {%0,%1,%2,%3};\n"
        : "+f"(d[0]), "+f"(d[1]), "+f"(d[2]), "+f"(d[3])
        : "r"(a[0]), "r"(a[1]), "r"(a[2]), "r"(a[3]), "r"(b[0]), "r"(b[1]));
}

// ---------------- kernel 0: init ----------------
__global__ void init_kernel() {
    int gtid = blockIdx.x * blockDim.x + threadIdx.x;
    int stride = gridDim.x * blockDim.x;
    for (int i = gtid; i < MTOT; i += stride) g_A[i] = 0.0f;
    for (int i = gtid; i < NSEG * IDIM; i += stride) g_cfraw[i] = 0.0f;
    if (gtid < NSEG) {
        g_segmax[gtid] = -1e30f;
        g_segsum[gtid] = 0.0f;
        g_counts[gtid] = 0;
    }
}

// ---------------- kernel 1: x = relu([h | emb[cid]] @ W_fuse + b_fuse)  (tf32 mma) ----------------
// block tile 128(M)x64(N), 8 warps as 4x2 -> warp tile 32x32; K=512 in BK=32 slabs.
// Fragment smem layouts are conflict-free: As stride 36 (bank=gid*4+tig), Bs stride 72 (bank=tig*8+gid).
__global__ __launch_bounds__(256) void fuse_mma_kernel(
    const float* __restrict__ h, const int* __restrict__ cids,
    const float* __restrict__ emb, const float* __restrict__ Wf,
    const float* __restrict__ bf)
{
    __shared__ uint32_t As[128][36];
    __shared__ uint32_t Bs[32][72];
    __shared__ float sWe[8][64];     // W_fuse rows 512..519 for this n-block
    __shared__ float sbf[64];
    __shared__ float semb[NCLUST * EMBD];
    __shared__ int   scids[128];

    const int tid  = threadIdx.x;
    const int m0   = blockIdx.y * 128;
    const int n0   = blockIdx.x * 64;
    const int warp = tid >> 5, lane = tid & 31;
    const int gid  = lane >> 2, tig = lane & 3;
    const int wm   = (warp >> 1) * 32, wn = (warp & 1) * 32;

    if (tid < 128) { int c = cids[m0 + tid]; scids[tid] = min(max(c, 0), CC); }
    if (tid < 64)  sbf[tid] = bf[n0 + tid];
    if (tid < NCLUST * EMBD) semb[tid] = emb[tid];
    for (int t = tid; t < 8 * 64; t += 256) {
        int e = t >> 6, n = t & 63;
        sWe[e][n] = Wf[(size_t)(IDIM + e) * IDIM + n0 + n];
    }

    float acc[2][4][4];
#pragma unroll
    for (int mi = 0; mi < 2; mi++)
#pragma unroll
        for (int ni = 0; ni < 4; ni++)
#pragma unroll
            for (int c = 0; c < 4; c++) acc[mi][ni][c] = 0.0f;

    for (int kt = 0; kt < 16; kt++) {
        const int k0 = kt * 32;
#pragma unroll
        for (int i = 0; i < 4; i++) {
            int idx = i * 256 + tid;
            int row = idx >> 3, c4 = (idx & 7) * 4;
            float4 v = *(const float4*)&h[(size_t)(m0 + row) * IDIM + k0 + c4];
            As[row][c4 + 0] = f2tf32(v.x);
            As[row][c4 + 1] = f2tf32(v.y);
            As[row][c4 + 2] = f2tf32(v.z);
            As[row][c4 + 3] = f2tf32(v.w);
        }
#pragma unroll
        for (int i = 0; i < 2; i++) {
            int idx = i * 256 + tid;
            int kk = idx >> 4, c4 = (idx & 15) * 4;
            float4 v = *(const float4*)&Wf[(size_t)(k0 + kk) * IDIM + n0 + c4];
            Bs[kk][c4 + 0] = f2tf32(v.x);
            Bs[kk][c4 + 1] = f2tf32(v.y);
            Bs[kk][c4 + 2] = f2tf32(v.z);
            Bs[kk][c4 + 3] = f2tf32(v.w);
        }
        __syncthreads();
#pragma unroll
        for (int ks = 0; ks < 4; ks++) {
            const int kb = ks * 8;
            uint32_t af[2][4], bfr[4][2];
#pragma unroll
            for (int mi = 0; mi < 2; mi++) {
                int mr = wm + mi * 16 + gid;
                af[mi][0] = As[mr][kb + tig];
                af[mi][1] = As[mr + 8][kb + tig];
                af[mi][2] = As[mr][kb + tig + 4];
                af[mi][3] = As[mr + 8][kb + tig + 4];
            }
#pragma unroll
            for (int ni = 0; ni < 4; ni++) {
                int nc = wn + ni * 8 + gid;
                bfr[ni][0] = Bs[kb + tig][nc];
                bfr[ni][1] = Bs[kb + tig + 4][nc];
            }
#pragma unroll
            for (int mi = 0; mi < 2; mi++)
#pragma unroll
                for (int ni = 0; ni < 4; ni++)
                    mma_tf32(acc[mi][ni], af[mi], bfr[ni]);
        }
        __syncthreads();
    }

    // epilogue: emb contribution + bias + relu, store as float2
#pragma unroll
    for (int mi = 0; mi < 2; mi++) {
#pragma unroll
        for (int half = 0; half < 2; half++) {
            int ml = wm + mi * 16 + gid + half * 8;
            int m  = m0 + ml;
            const float* ev = &semb[scids[ml] * EMBD];
#pragma unroll
            for (int ni = 0; ni < 4; ni++) {
                int nl = wn + ni * 8 + 2 * tig;
                float e0 = 0.0f, e1 = 0.0f;
#pragma unroll
                for (int e = 0; e < 8; e++) {
                    e0 += ev[e] * sWe[e][nl];
                    e1 += ev[e] * sWe[e][nl + 1];
                }
                float o0 = fmaxf(acc[mi][ni][half * 2 + 0] + e0 + sbf[nl],     0.0f);
                float o1 = fmaxf(acc[mi][ni][half * 2 + 1] + e1 + sbf[nl + 1], 0.0f);
                *(float2*)&g_x[(size_t)m * IDIM + n0 + nl] = make_float2(o0, o1);
            }
        }
    }
}

// ---------------- kernel 2: intra gated attention logits (tf32 mma, dual GEMM) ----------------
// block tile 128(M)x64(D) covering one quarter of D=256; computes BOTH x@Wa1 and x@Wb1,
// applies tanh*sigmoid*Wc1 in-register, reduces over d, atomicAdds into g_A.
__global__ __launch_bounds__(256) void attn1_mma_kernel(
    const float* __restrict__ Wa1, const float* __restrict__ ba1,
    const float* __restrict__ Wb1, const float* __restrict__ bb1,
    const float* __restrict__ Wc1)
{
    __shared__ uint32_t As[128][36];
    __shared__ uint32_t Ba[32][72];
    __shared__ uint32_t Bb[32][72];
    __shared__ float sba[64], sbb[64], swc[64];
    __shared__ float sA[128];

    const int tid  = threadIdx.x;
    const int m0   = blockIdx.y * 128;
    const int d0   = blockIdx.x * 64;
    const int warp = tid >> 5, lane = tid & 31;
    const int gid  = lane >> 2, tig = lane & 3;
    const int wm   = (warp >> 1) * 32, wn = (warp & 1) * 32;

    if (tid < 64) { sba[tid] = ba1[d0 + tid]; sbb[tid] = bb1[d0 + tid]; swc[tid] = Wc1[d0 + tid]; }
    if (tid < 128) sA[tid] = 0.0f;

    float acca[2][4][4], accg[2][4][4];
#pragma unroll
    for (int mi = 0; mi < 2; mi++)
#pragma unroll
        for (int ni = 0; ni < 4; ni++)
#pragma unroll
            for (int c = 0; c < 4; c++) { acca[mi][ni][c] = 0.0f; accg[mi][ni][c] = 0.0f; }

    for (int kt = 0; kt < 16; kt++) {
        const int k0 = kt * 32;
#pragma unroll
        for (int i = 0; i < 4; i++) {
            int idx = i * 256 + tid;
            int row = idx >> 3, c4 = (idx & 7) * 4;
            float4 v = *(const float4*)&g_x[(size_t)(m0 + row) * IDIM + k0 + c4];
            As[row][c4 + 0] = f2tf32(v.x);
            As[row][c4 + 1] = f2tf32(v.y);
            As[row][c4 + 2] = f2tf32(v.z);
            As[row][c4 + 3] = f2tf32(v.w);
        }
#pragma unroll
        for (int i = 0; i < 2; i++) {
            int idx = i * 256 + tid;
            int kk = idx >> 4, c4 = (idx & 15) * 4;
            float4 va = *(const float4*)&Wa1[(size_t)(k0 + kk) * DDIM + d0 + c4];
            Ba[kk][c4 + 0] = f2tf32(va.x);
            Ba[kk][c4 + 1] = f2tf32(va.y);
            Ba[kk][c4 + 2] = f2tf32(va.z);
            Ba[kk][c4 + 3] = f2tf32(va.w);
            float4 vb = *(const float4*)&Wb1[(size_t)(k0 + kk) * DDIM + d0 + c4];
            Bb[kk][c4 + 0] = f2tf32(vb.x);
            Bb[kk][c4 + 1] = f2tf32(vb.y);
            Bb[kk][c4 + 2] = f2tf32(vb.z);
            Bb[kk][c4 + 3] = f2tf32(vb.w);
        }
        __syncthreads();
#pragma unroll
        for (int ks = 0; ks < 4; ks++) {
            const int kb = ks * 8;
            uint32_t af[2][4];
#pragma unroll
            for (int mi = 0; mi < 2; mi++) {
                int mr = wm + mi * 16 + gid;
                af[mi][0] = As[mr][kb + tig];
                af[mi][1] = As[mr + 8][kb + tig];
                af[mi][2] = As[mr][kb + tig + 4];
                af[mi][3] = As[mr + 8][kb + tig + 4];
            }
#pragma unroll
            for (int ni = 0; ni < 4; ni++) {
                int nc = wn + ni * 8 + gid;
                uint32_t ba_[2], bb_[2];
                ba_[0] = Ba[kb + tig][nc];  ba_[1] = Ba[kb + tig + 4][nc];
                bb_[0] = Bb[kb + tig][nc];  bb_[1] = Bb[kb + tig + 4][nc];
#pragma unroll
                for (int mi = 0; mi < 2; mi++) {
                    mma_tf32(acca[mi][ni], af[mi], ba_);
                    mma_tf32(accg[mi][ni], af[mi], bb_);
                }
            }
        }
        __syncthreads();
    }

    // epilogue: gated pointwise + row reduction over this 64-d slab
    float rsum[2][2];
    rsum[0][0] = rsum[0][1] = rsum[1][0] = rsum[1][1] = 0.0f;
#pragma unroll
    for (int mi = 0; mi < 2; mi++)
#pragma unroll
        for (int ni = 0; ni < 4; ni++) {
            int nl = wn + ni * 8 + 2 * tig;
#pragma unroll
            for (int half = 0; half < 2; half++) {
#pragma unroll
                for (int col = 0; col < 2; col++) {
                    int dl = nl + col;
                    float va = tanhf(acca[mi][ni][half * 2 + col] + sba[dl]);
                    float vg = sigmoidf_(accg[mi][ni][half * 2 + col] + sbb[dl]);
                    rsum[mi][half] += va * vg * swc[dl];
                }
            }
        }
#pragma unroll
    for (int mi = 0; mi < 2; mi++)
#pragma unroll
        for (int half = 0; half < 2; half++) {
            float v = rsum[mi][half];
            v += __shfl_xor_sync(0xffffffffu, v, 1);
            v += __shfl_xor_sync(0xffffffffu, v, 2);
            if (tig == 0) atomicAdd(&sA[wm + mi * 16 + gid + half * 8], v);
        }
    __syncthreads();
    if (tid < 128) atomicAdd(&g_A[m0 + tid], sA[tid]);
}

// ---------------- kernel 3: segment max ----------------
__global__ void segmax_kernel(const int* __restrict__ cids) {
    __shared__ float smax[NSEG];
    const int tid = threadIdx.x;
    if (tid < NSEG) smax[tid] = -1e30f;
    __syncthreads();
    for (int m = blockIdx.x * blockDim.x + tid; m < MTOT; m += gridDim.x * blockDim.x) {
        int cid = cids[m];
        cid = min(max(cid, 0), CC);
        int seg = (m >> 14) * NCLUST + cid;
        atomicMaxFloat(&smax[seg], g_A[m]);
    }
    __syncthreads();
    if (tid < NSEG) atomicMaxFloat(&g_segmax[tid], smax[tid]);
}

// ---------------- kernel 4: ex = exp(A - segmax), segment sum + counts ----------------
__global__ void segsum_kernel(const int* __restrict__ cids) {
    __shared__ float ssum[NSEG];
    __shared__ int   scnt[NSEG];
    const int tid = threadIdx.x;
    if (tid < NSEG) { ssum[tid] = 0.0f; scnt[tid] = 0; }
    __syncthreads();
    for (int m = blockIdx.x * blockDim.x + tid; m < MTOT; m += gridDim.x * blockDim.x) {
        int cid = cids[m];
        cid = min(max(cid, 0), CC);
        int seg = (m >> 14) * NCLUST + cid;
        float ex = expf(g_A[m] - g_segmax[seg]);
        g_ex[m] = ex;
        atomicAdd(&ssum[seg], ex);
        atomicAdd(&scnt[seg], 1);
    }
    __syncthreads();
    if (tid < NSEG) {
        atomicAdd(&g_segsum[tid], ssum[tid]);
        atomicAdd(&g_counts[tid], scnt[tid]);
    }
}

// ---------------- kernel 5: cfraw[seg] += w * x[m]   (w = ex/denom) ----------------
__global__ __launch_bounds__(256) void cfeat_kernel(const int* __restrict__ cids) {
    __shared__ float sh[NCLUST][IDIM];
    const int tid = threadIdx.x;
    const int b     = blockIdx.x >> 6;
    const int chunk = blockIdx.x & 63;
    for (int i = tid; i < NCLUST * IDIM; i += 256) ((float*)sh)[i] = 0.0f;
    __syncthreads();
    const int mbase = b * NPB + chunk * 256;
    for (int r = 0; r < 256; r++) {
        int m = mbase + r;
        int cid = cids[m];
        cid = min(max(cid, 0), CC);
        float w = g_ex[m] / g_segsum[b * NCLUST + cid];
        const float* xr = &g_x[(size_t)m * IDIM];
        sh[cid][tid]       += w * xr[tid];
        sh[cid][tid + 256] += w * xr[tid + 256];
    }
    __syncthreads();
    for (int c = 0; c < NCLUST; c++) {
        atomicAdd(&g_cfraw[(b * NCLUST + c) * IDIM + tid],       sh[c][tid]);
        atomicAdd(&g_cfraw[(b * NCLUST + c) * IDIM + tid + 256], sh[c][tid + 256]);
    }
}

// ---------------- kernel 6: cfeat = relu(cfraw @ W_intra + b_intra)  [88,512] ----------------
__global__ __launch_bounds__(256) void intra_kernel(
    const float* __restrict__ Wi, const float* __restrict__ bi)
{
    __shared__ float xr[IDIM];
    const int s = blockIdx.x, tid = threadIdx.x;
    xr[tid]       = g_cfraw[s * IDIM + tid];
    xr[tid + 256] = g_cfraw[s * IDIM + tid + 256];
    __syncthreads();
#pragma unroll
    for (int jj = 0; jj < 2; jj++) {
        int j = tid + jj * 256;
        float acc = bi[j];
        for (int k = 0; k < IDIM; k++) acc += xr[k] * Wi[(size_t)k * IDIM + j];
        g_cfeat[s * IDIM + j] = fmaxf(acc, 0.0f);
    }
}

// ---------------- kernel 7: inter-cluster gated logits A2[88] ----------------
__global__ __launch_bounds__(256) void attn2_kernel(
    const float* __restrict__ Wa2, const float* __restrict__ ba2,
    const float* __restrict__ Wb2, const float* __restrict__ bb2,
    const float* __restrict__ Wc2, const float* __restrict__ bc2)
{
    __shared__ float xr[IDIM];
    __shared__ float red[256];
    const int s = blockIdx.x, tid = threadIdx.x;
    xr[tid]       = g_cfeat[s * IDIM + tid];
    xr[tid + 256] = g_cfeat[s * IDIM + tid + 256];
    __syncthreads();
    float aa = ba2[tid], bb = bb2[tid];
    for (int k = 0; k < IDIM; k++) {
        float xv = xr[k];
        aa += xv * Wa2[(size_t)k * DDIM + tid];
        bb += xv * Wb2[(size_t)k * DDIM + tid];
    }
    red[tid] = tanhf(aa) * sigmoidf_(bb) * Wc2[tid];
    __syncthreads();
    for (int off = 128; off > 0; off >>= 1) {
        if (tid < off) red[tid] += red[tid + off];
        __syncthreads();
    }
    if (tid == 0)
        g_A2[s] = (g_counts[s] > 0) ? (red[0] + bc2[0]) : -1e30f;
}

// ---------------- kernel 8: per-batch softmax, pooling, classifier ----------------
__global__ __launch_bounds__(256) void final_kernel(
    const float* __restrict__ Wint, const float* __restrict__ bint,
    const float* __restrict__ Wcls, const float* __restrict__ bcls,
    float* __restrict__ out)
{
    __shared__ float sWs[NCLUST];
    __shared__ float sl[IDIM];
    __shared__ float st2[256];
    __shared__ float red[256];
    const int b = blockIdx.x, tid = threadIdx.x;

    if (tid == 0) {
        float mx = -1e30f;
        for (int c = 0; c < NCLUST; c++) mx = fmaxf(mx, g_A2[b * NCLUST + c]);
        float e[NCLUST]; float sum = 0.0f;
        for (int c = 0; c < NCLUST; c++) { e[c] = expf(g_A2[b * NCLUST + c] - mx); sum += e[c]; }
        for (int c = 0; c < NCLUST; c++) sWs[c] = e[c] / sum;
    }
    __syncthreads();

#pragma unroll
    for (int jj = 0; jj < 2; jj++) {
        int j = tid + jj * 256;
        float s = 0.0f;
        for (int c = 0; c < NCLUST; c++)
            s += sWs[c] * g_cfeat[(b * NCLUST + c) * IDIM + j];
        sl[j] = s;
    }
    __syncthreads();

    float acc = bint[tid];
    for (int k = 0; k < IDIM; k++) acc += sl[k] * Wint[(size_t)k * 256 + tid];
    st2[tid] = fmaxf(acc, 0.0f);
    __syncthreads();

    red[tid] = st2[tid] * Wcls[tid * 2 + 0];
    __syncthreads();
    for (int off = 128; off > 0; off >>= 1) {
        if (tid < off) red[tid] += red[tid + off];
        __syncthreads();
    }
    if (tid == 0) out[b * 2 + 0] = red[0] + bcls[0];
    __syncthreads();

    red[tid] = st2[tid] * Wcls[tid * 2 + 1];
    __syncthreads();
    for (int off = 128; off > 0; off >>= 1) {
        if (tid < off) red[tid] += red[tid + off];
        __syncthreads();
    }
    if (tid == 0) out[b * 2 + 1] = red[0] + bcls[1];
}

// ---------------- launch ----------------
extern "C" void kernel_launch(void* const* d_in, const int* in_sizes, int n_in,
                              void* d_out, int out_size)
{
    const float* h       = (const float*)d_in[0];
    const int*   cids    = (const int*)  d_in[1];
    const float* emb     = (const float*)d_in[2];
    const float* W_fuse  = (const float*)d_in[3];
    const float* b_fuse  = (const float*)d_in[4];
    const float* Wa1     = (const float*)d_in[5];
    const float* ba1     = (const float*)d_in[6];
    const float* Wb1     = (const float*)d_in[7];
    const float* bb1     = (const float*)d_in[8];
    const float* Wc1     = (const float*)d_in[9];
    // d_in[10] = bc1 (unused: constant shift is softmax-invariant)
    const float* W_intra = (const float*)d_in[11];
    const float* b_intra = (const float*)d_in[12];
    const float* Wa2     = (const float*)d_in[13];
    const float* ba2     = (const float*)d_in[14];
    const float* Wb2     = (const float*)d_in[15];
    const float* bb2     = (const float*)d_in[16];
    const float* Wc2     = (const float*)d_in[17];
    const float* bc2     = (const float*)d_in[18];
    const float* W_inter = (const float*)d_in[19];
    const float* b_inter = (const float*)d_in[20];
    const float* W_cls   = (const float*)d_in[21];
    const float* b_cls   = (const float*)d_in[22];
    float* out = (float*)d_out;

    init_kernel<<<256, 256>>>();
    fuse_mma_kernel<<<dim3(IDIM / 64, MTOT / 128), 256>>>(h, cids, emb, W_fuse, b_fuse);
    attn1_mma_kernel<<<dim3(DDIM / 64, MTOT / 128), 256>>>(Wa1, ba1, Wb1, bb1, Wc1);
    segmax_kernel<<<256, 256>>>(cids);
    segsum_kernel<<<256, 256>>>(cids);
    cfeat_kernel<<<BATCH * 64, 256>>>(cids);
    intra_kernel<<<NSEG, 256>>>(W_intra, b_intra);
    attn2_kernel<<<NSEG, 256>>>(Wa2, ba2, Wb2, bb2, Wc2, bc2);
    final_kernel<<<BATCH, 256>>>(W_inter, b_inter, W_cls, b_cls, out);
}

// round 6
// speedup vs baseline: 3.0362x; 1.2000x over previous
#include <cuda_runtime.h>
#include <math.h>
#include <stdint.h>

// ---------------- problem constants ----------------
#define CC     10
#define NCLUST 11            // C+1
#define NSEG   88            // B * (C+1)
#define BATCH  8
#define NPB    16384         // tokens per batch
#define MTOT   131072        // B*N
#define IDIM   512
#define EMBD   8
#define DDIM   256

// ---------------- scratch (static device globals) ----------------
__device__ float g_x[(size_t)MTOT * IDIM];     // fused features, 256 MiB
__device__ float g_A[MTOT];                    // intra attention logits (bc1 folded out: softmax-invariant)
__device__ float g_ex[MTOT];                   // exp(A - segmax)
__device__ float g_segmax[NSEG];
__device__ float g_segsum[NSEG];
__device__ int   g_counts[NSEG];
__device__ float g_cfraw[NSEG * IDIM];
__device__ float g_cfeat[NSEG * IDIM];
__device__ float g_A2[NSEG];

// ---------------- helpers ----------------
__device__ __forceinline__ void atomicMaxFloat(float* addr, float val) {
    int* ia = (int*)addr;
    int old = *ia;
    while (__int_as_float(old) < val) {
        int assumed = old;
        old = atomicCAS(ia, assumed, __float_as_int(val));
        if (old == assumed) break;
    }
}

__device__ __forceinline__ float sigmoidf_(float v) {
    return 1.0f / (1.0f + expf(-v));
}

__device__ __forceinline__ uint32_t smem_u32(const void* p) {
    return (uint32_t)__cvta_generic_to_shared(p);
}
__device__ __forceinline__ void cp16(uint32_t dst, const void* src) {
    asm volatile("cp.async.cg.shared.global [%0], [%1], 16;" :: "r"(dst), "l"(src));
}
#define CP_COMMIT()  asm volatile("cp.async.commit_group;")
#define CP_WAIT1()   asm volatile("cp.async.wait_group 1;")
#define CP_WAIT0()   asm volatile("cp.async.wait_group 0;")

// m16n8k8 tf32 mma, row.col, fp32 accum. Operands carry raw f32 bits;
// HW truncates the low mantissa (~2^-10 rel quantization, fine vs 1e-3 budget).
__device__ __forceinline__ void mma_tf32(float* d, const uint32_t* a, const uint32_t* b) {
    asm volatile(
        "mma.sync.aligned.m16n8k8.row.col.f32.tf32.tf32.f32 "
        "{%0,%1,%2,%3}, {%4,%5,%6,%7}, {%8,%9}, {%0,%1,%2,%3};\n"
        : "+f"(d[0]), "+f"(d[1]), "+f"(d[2]), "+f"(d[3])
        : "r"(a[0]), "r"(a[1]), "r"(a[2]), "r"(a[3]), "r"(b[0]), "r"(b[1]));
}

// ---------------- kernel 0: init ----------------
__global__ void init_kernel() {
    int gtid = blockIdx.x * blockDim.x + threadIdx.x;
    int stride = gridDim.x * blockDim.x;
    for (int i = gtid; i < MTOT; i += stride) g_A[i] = 0.0f;
    for (int i = gtid; i < NSEG * IDIM; i += stride) g_cfraw[i] = 0.0f;
    if (gtid < NSEG) {
        g_segmax[gtid] = -1e30f;
        g_segsum[gtid] = 0.0f;
        g_counts[gtid] = 0;
    }
}

// ---------------- kernel 1: x = relu([h | emb[cid]] @ W_fuse + b_fuse) ----------------
// tf32 mma, block 128(M) x 128(N), 8 warps 4x2 -> warp 32x64, BK=32, 2-stage cp.async pipeline.
// As stride 36 (frag bank = 4*gid+tig bijective), Bs stride 136 (frag bank = 8*tig+gid bijective).
#define F_AS_STRIDE 36
#define F_BS_STRIDE 136
#define F_AS_ELEMS  (128 * F_AS_STRIDE)
#define F_BS_ELEMS  (32 * F_BS_STRIDE)
#define F_DSMEM_BYTES ((2 * F_AS_ELEMS + 2 * F_BS_ELEMS) * 4)

__global__ __launch_bounds__(256) void fuse_mma_kernel(
    const float* __restrict__ h, const int* __restrict__ cids,
    const float* __restrict__ emb, const float* __restrict__ Wf,
    const float* __restrict__ bf)
{
    extern __shared__ float dsm[];
    float* Asb = dsm;                       // [2][128][36]
    float* Bsb = dsm + 2 * F_AS_ELEMS;      // [2][32][136]
    __shared__ float sWe[8][128];
    __shared__ float sbf[128];
    __shared__ float semb[NCLUST * EMBD];
    __shared__ int   scids[128];

    const int tid  = threadIdx.x;
    const int m0   = blockIdx.y * 128;
    const int n0   = blockIdx.x * 128;
    const int warp = tid >> 5, lane = tid & 31;
    const int gid  = lane >> 2, tig = lane & 3;
    const int wm   = (warp >> 1) * 32, wn = (warp & 1) * 64;

    if (tid < 128) { int c = cids[m0 + tid]; scids[tid] = min(max(c, 0), CC); }
    if (tid < 128) sbf[tid] = bf[n0 + tid];
    if (tid < NCLUST * EMBD) semb[tid] = emb[tid];
    for (int t = tid; t < 8 * 128; t += 256) {
        int e = t >> 7, n = t & 127;
        sWe[e][n] = Wf[(size_t)(IDIM + e) * IDIM + n0 + n];
    }

    float acc[2][8][4];
#pragma unroll
    for (int mi = 0; mi < 2; mi++)
#pragma unroll
        for (int ni = 0; ni < 8; ni++)
#pragma unroll
            for (int c = 0; c < 4; c++) acc[mi][ni][c] = 0.0f;

    // slab loader: global -> smem stage st via cp.async (raw f32 bits)
    auto load_slab = [&](int kt, int st) {
        const int k0 = kt * 32;
        float* a = Asb + st * F_AS_ELEMS;
        float* b = Bsb + st * F_BS_ELEMS;
#pragma unroll
        for (int i = 0; i < 4; i++) {
            int idx = i * 256 + tid;
            int row = idx >> 3, c4 = (idx & 7) * 4;
            cp16(smem_u32(a + row * F_AS_STRIDE + c4),
                 h + (size_t)(m0 + row) * IDIM + k0 + c4);
        }
#pragma unroll
        for (int i = 0; i < 4; i++) {
            int idx = i * 256 + tid;
            int kk = idx >> 5, c4 = (idx & 31) * 4;
            cp16(smem_u32(b + kk * F_BS_STRIDE + c4),
                 Wf + (size_t)(k0 + kk) * IDIM + n0 + c4);
        }
    };

    load_slab(0, 0);
    CP_COMMIT();

    for (int kt = 0; kt < 16; kt++) {
        const int cur = kt & 1;
        if (kt < 15) { load_slab(kt + 1, cur ^ 1); CP_COMMIT(); CP_WAIT1(); }
        else         { CP_WAIT0(); }
        __syncthreads();
        const uint32_t* a = (const uint32_t*)(Asb + cur * F_AS_ELEMS);
        const uint32_t* b = (const uint32_t*)(Bsb + cur * F_BS_ELEMS);
#pragma unroll
        for (int ks = 0; ks < 4; ks++) {
            const int kb = ks * 8;
            uint32_t af[2][4], bfr[8][2];
#pragma unroll
            for (int mi = 0; mi < 2; mi++) {
                int mr = wm + mi * 16 + gid;
                af[mi][0] = a[mr * F_AS_STRIDE + kb + tig];
                af[mi][1] = a[(mr + 8) * F_AS_STRIDE + kb + tig];
                af[mi][2] = a[mr * F_AS_STRIDE + kb + tig + 4];
                af[mi][3] = a[(mr + 8) * F_AS_STRIDE + kb + tig + 4];
            }
#pragma unroll
            for (int ni = 0; ni < 8; ni++) {
                int nc = wn + ni * 8 + gid;
                bfr[ni][0] = b[(kb + tig) * F_BS_STRIDE + nc];
                bfr[ni][1] = b[(kb + tig + 4) * F_BS_STRIDE + nc];
            }
#pragma unroll
            for (int mi = 0; mi < 2; mi++)
#pragma unroll
                for (int ni = 0; ni < 8; ni++)
                    mma_tf32(acc[mi][ni], af[mi], bfr[ni]);
        }
        __syncthreads();
    }

    // epilogue: emb contribution + bias + relu
#pragma unroll
    for (int mi = 0; mi < 2; mi++) {
#pragma unroll
        for (int half = 0; half < 2; half++) {
            int ml = wm + mi * 16 + gid + half * 8;
            int m  = m0 + ml;
            const float* ev = &semb[scids[ml] * EMBD];
#pragma unroll
            for (int ni = 0; ni < 8; ni++) {
                int nl = wn + ni * 8 + 2 * tig;
                float e0 = 0.0f, e1 = 0.0f;
#pragma unroll
                for (int e = 0; e < 8; e++) {
                    e0 += ev[e] * sWe[e][nl];
                    e1 += ev[e] * sWe[e][nl + 1];
                }
                float o0 = fmaxf(acc[mi][ni][half * 2 + 0] + e0 + sbf[nl],     0.0f);
                float o1 = fmaxf(acc[mi][ni][half * 2 + 1] + e1 + sbf[nl + 1], 0.0f);
                *(float2*)&g_x[(size_t)m * IDIM + n0 + nl] = make_float2(o0, o1);
            }
        }
    }
}

// ---------------- kernel 2: intra gated attention logits (dual tf32 mma, pipelined) ----------------
// block 128(M) x 64(D), 8 warps 4x2 -> warp 32x32, computes x@Wa1 and x@Wb1 together.
#define A_AS_STRIDE 36
#define A_BS_STRIDE 72
#define A_AS_ELEMS  (128 * A_AS_STRIDE)
#define A_BS_ELEMS  (32 * A_BS_STRIDE)
#define A_DSMEM_BYTES ((2 * A_AS_ELEMS + 4 * A_BS_ELEMS) * 4)

__global__ __launch_bounds__(256) void attn1_mma_kernel(
    const float* __restrict__ Wa1, const float* __restrict__ ba1,
    const float* __restrict__ Wb1, const float* __restrict__ bb1,
    const float* __restrict__ Wc1)
{
    extern __shared__ float dsm[];
    float* Asb = dsm;                                  // [2][128][36]
    float* Bab = dsm + 2 * A_AS_ELEMS;                 // [2][32][72]
    float* Bbb = dsm + 2 * A_AS_ELEMS + 2 * A_BS_ELEMS;// [2][32][72]
    __shared__ float sba[64], sbb[64], swc[64];
    __shared__ float sA[128];

    const int tid  = threadIdx.x;
    const int m0   = blockIdx.y * 128;
    const int d0   = blockIdx.x * 64;
    const int warp = tid >> 5, lane = tid & 31;
    const int gid  = lane >> 2, tig = lane & 3;
    const int wm   = (warp >> 1) * 32, wn = (warp & 1) * 32;

    if (tid < 64) { sba[tid] = ba1[d0 + tid]; sbb[tid] = bb1[d0 + tid]; swc[tid] = Wc1[d0 + tid]; }
    if (tid < 128) sA[tid] = 0.0f;

    float acca[2][4][4], accg[2][4][4];
#pragma unroll
    for (int mi = 0; mi < 2; mi++)
#pragma unroll
        for (int ni = 0; ni < 4; ni++)
#pragma unroll
            for (int c = 0; c < 4; c++) { acca[mi][ni][c] = 0.0f; accg[mi][ni][c] = 0.0f; }

    auto load_slab = [&](int kt, int st) {
        const int k0 = kt * 32;
        float* a  = Asb + st * A_AS_ELEMS;
        float* ba = Bab + st * A_BS_ELEMS;
        float* bb = Bbb + st * A_BS_ELEMS;
#pragma unroll
        for (int i = 0; i < 4; i++) {
            int idx = i * 256 + tid;
            int row = idx >> 3, c4 = (idx & 7) * 4;
            cp16(smem_u32(a + row * A_AS_STRIDE + c4),
                 g_x + (size_t)(m0 + row) * IDIM + k0 + c4);
        }
#pragma unroll
        for (int i = 0; i < 2; i++) {
            int idx = i * 256 + tid;
            int kk = idx >> 4, c4 = (idx & 15) * 4;
            cp16(smem_u32(ba + kk * A_BS_STRIDE + c4),
                 Wa1 + (size_t)(k0 + kk) * DDIM + d0 + c4);
            cp16(smem_u32(bb + kk * A_BS_STRIDE + c4),
                 Wb1 + (size_t)(k0 + kk) * DDIM + d0 + c4);
        }
    };

    load_slab(0, 0);
    CP_COMMIT();

    for (int kt = 0; kt < 16; kt++) {
        const int cur = kt & 1;
        if (kt < 15) { load_slab(kt + 1, cur ^ 1); CP_COMMIT(); CP_WAIT1(); }
        else         { CP_WAIT0(); }
        __syncthreads();
        const uint32_t* a  = (const uint32_t*)(Asb + cur * A_AS_ELEMS);
        const uint32_t* ba = (const uint32_t*)(Bab + cur * A_BS_ELEMS);
        const uint32_t* bb = (const uint32_t*)(Bbb + cur * A_BS_ELEMS);
#pragma unroll
        for (int ks = 0; ks < 4; ks++) {
            const int kb = ks * 8;
            uint32_t af[2][4];
#pragma unroll
            for (int mi = 0; mi < 2; mi++) {
                int mr = wm + mi * 16 + gid;
                af[mi][0] = a[mr * A_AS_STRIDE + kb + tig];
                af[mi][1] = a[(mr + 8) * A_AS_STRIDE + kb + tig];
                af[mi][2] = a[mr * A_AS_STRIDE + kb + tig + 4];
                af[mi][3] = a[(mr + 8) * A_AS_STRIDE + kb + tig + 4];
            }
#pragma unroll
            for (int ni = 0; ni < 4; ni++) {
                int nc = wn + ni * 8 + gid;
                uint32_t ba_[2], bb_[2];
                ba_[0] = ba[(kb + tig) * A_BS_STRIDE + nc];
                ba_[1] = ba[(kb + tig + 4) * A_BS_STRIDE + nc];
                bb_[0] = bb[(kb + tig) * A_BS_STRIDE + nc];
                bb_[1] = bb[(kb + tig + 4) * A_BS_STRIDE + nc];
#pragma unroll
                for (int mi = 0; mi < 2; mi++) {
                    mma_tf32(acca[mi][ni], af[mi], ba_);
                    mma_tf32(accg[mi][ni], af[mi], bb_);
                }
            }
        }
        __syncthreads();
    }

    // epilogue: gated pointwise + row reduction over this 64-d slab
    float rsum[2][2];
    rsum[0][0] = rsum[0][1] = rsum[1][0] = rsum[1][1] = 0.0f;
#pragma unroll
    for (int mi = 0; mi < 2; mi++)
#pragma unroll
        for (int ni = 0; ni < 4; ni++) {
            int nl = wn + ni * 8 + 2 * tig;
#pragma unroll
            for (int half = 0; half < 2; half++) {
#pragma unroll
                for (int col = 0; col < 2; col++) {
                    int dl = nl + col;
                    float va = tanhf(acca[mi][ni][half * 2 + col] + sba[dl]);
                    float vg = sigmoidf_(accg[mi][ni][half * 2 + col] + sbb[dl]);
                    rsum[mi][half] += va * vg * swc[dl];
                }
            }
        }
#pragma unroll
    for (int mi = 0; mi < 2; mi++)
#pragma unroll
        for (int half = 0; half < 2; half++) {
            float v = rsum[mi][half];
            v += __shfl_xor_sync(0xffffffffu, v, 1);
            v += __shfl_xor_sync(0xffffffffu, v, 2);
            if (tig == 0) atomicAdd(&sA[wm + mi * 16 + gid + half * 8], v);
        }
    __syncthreads();
    if (tid < 128) atomicAdd(&g_A[m0 + tid], sA[tid]);
}

// ---------------- kernel 3: segment max ----------------
__global__ void segmax_kernel(const int* __restrict__ cids) {
    __shared__ float smax[NSEG];
    const int tid = threadIdx.x;
    if (tid < NSEG) smax[tid] = -1e30f;
    __syncthreads();
    for (int m = blockIdx.x * blockDim.x + tid; m < MTOT; m += gridDim.x * blockDim.x) {
        int cid = cids[m];
        cid = min(max(cid, 0), CC);
        int seg = (m >> 14) * NCLUST + cid;
        atomicMaxFloat(&smax[seg], g_A[m]);
    }
    __syncthreads();
    if (tid < NSEG) atomicMaxFloat(&g_segmax[tid], smax[tid]);
}

// ---------------- kernel 4: ex = exp(A - segmax), segment sum + counts ----------------
__global__ void segsum_kernel(const int* __restrict__ cids) {
    __shared__ float ssum[NSEG];
    __shared__ int   scnt[NSEG];
    const int tid = threadIdx.x;
    if (tid < NSEG) { ssum[tid] = 0.0f; scnt[tid] = 0; }
    __syncthreads();
    for (int m = blockIdx.x * blockDim.x + tid; m < MTOT; m += gridDim.x * blockDim.x) {
        int cid = cids[m];
        cid = min(max(cid, 0), CC);
        int seg = (m >> 14) * NCLUST + cid;
        float ex = expf(g_A[m] - g_segmax[seg]);
        g_ex[m] = ex;
        atomicAdd(&ssum[seg], ex);
        atomicAdd(&scnt[seg], 1);
    }
    __syncthreads();
    if (tid < NSEG) {
        atomicAdd(&g_segsum[tid], ssum[tid]);
        atomicAdd(&g_counts[tid], scnt[tid]);
    }
}

// ---------------- kernel 5: cfraw[seg] += w * x[m] ----------------
__global__ __launch_bounds__(256) void cfeat_kernel(const int* __restrict__ cids) {
    __shared__ float sh[NCLUST][IDIM];
    const int tid = threadIdx.x;
    const int b     = blockIdx.x >> 6;
    const int chunk = blockIdx.x & 63;
    for (int i = tid; i < NCLUST * IDIM; i += 256) ((float*)sh)[i] = 0.0f;
    __syncthreads();
    const int mbase = b * NPB + chunk * 256;
    for (int r = 0; r < 256; r++) {
        int m = mbase + r;
        int cid = cids[m];
        cid = min(max(cid, 0), CC);
        float w = g_ex[m] / g_segsum[b * NCLUST + cid];
        const float* xr = &g_x[(size_t)m * IDIM];
        sh[cid][tid]       += w * xr[tid];
        sh[cid][tid + 256] += w * xr[tid + 256];
    }
    __syncthreads();
    for (int c = 0; c < NCLUST; c++) {
        atomicAdd(&g_cfraw[(b * NCLUST + c) * IDIM + tid],       sh[c][tid]);
        atomicAdd(&g_cfraw[(b * NCLUST + c) * IDIM + tid + 256], sh[c][tid + 256]);
    }
}

// ---------------- kernel 6: cfeat = relu(cfraw @ W_intra + b_intra)  [88,512] ----------------
__global__ __launch_bounds__(256) void intra_kernel(
    const float* __restrict__ Wi, const float* __restrict__ bi)
{
    __shared__ float xr[IDIM];
    const int s = blockIdx.x, tid = threadIdx.x;
    xr[tid]       = g_cfraw[s * IDIM + tid];
    xr[tid + 256] = g_cfraw[s * IDIM + tid + 256];
    __syncthreads();
#pragma unroll
    for (int jj = 0; jj < 2; jj++) {
        int j = tid + jj * 256;
        float acc = bi[j];
        for (int k = 0; k < IDIM; k++) acc += xr[k] * Wi[(size_t)k * IDIM + j];
        g_cfeat[s * IDIM + j] = fmaxf(acc, 0.0f);
    }
}

// ---------------- kernel 7: inter-cluster gated logits A2[88] ----------------
__global__ __launch_bounds__(256) void attn2_kernel(
    const float* __restrict__ Wa2, const float* __restrict__ ba2,
    const float* __restrict__ Wb2, const float* __restrict__ bb2,
    const float* __restrict__ Wc2, const float* __restrict__ bc2)
{
    __shared__ float xr[IDIM];
    __shared__ float red[256];
    const int s = blockIdx.x, tid = threadIdx.x;
    xr[tid]       = g_cfeat[s * IDIM + tid];
    xr[tid + 256] = g_cfeat[s * IDIM + tid + 256];
    __syncthreads();
    float aa = ba2[tid], bb = bb2[tid];
    for (int k = 0; k < IDIM; k++) {
        float xv = xr[k];
        aa += xv * Wa2[(size_t)k * DDIM + tid];
        bb += xv * Wb2[(size_t)k * DDIM + tid];
    }
    red[tid] = tanhf(aa) * sigmoidf_(bb) * Wc2[tid];
    __syncthreads();
    for (int off = 128; off > 0; off >>= 1) {
        if (tid < off) red[tid] += red[tid + off];
        __syncthreads();
    }
    if (tid == 0)
        g_A2[s] = (g_counts[s] > 0) ? (red[0] + bc2[0]) : -1e30f;
}

// ---------------- kernel 8: per-batch softmax, pooling, classifier ----------------
__global__ __launch_bounds__(256) void final_kernel(
    const float* __restrict__ Wint, const float* __restrict__ bint,
    const float* __restrict__ Wcls, const float* __restrict__ bcls,
    float* __restrict__ out)
{
    __shared__ float sWs[NCLUST];
    __shared__ float sl[IDIM];
    __shared__ float st2[256];
    __shared__ float red[256];
    const int b = blockIdx.x, tid = threadIdx.x;

    if (tid == 0) {
        float mx = -1e30f;
        for (int c = 0; c < NCLUST; c++) mx = fmaxf(mx, g_A2[b * NCLUST + c]);
        float e[NCLUST]; float sum = 0.0f;
        for (int c = 0; c < NCLUST; c++) { e[c] = expf(g_A2[b * NCLUST + c] - mx); sum += e[c]; }
        for (int c = 0; c < NCLUST; c++) sWs[c] = e[c] / sum;
    }
    __syncthreads();

#pragma unroll
    for (int jj = 0; jj < 2; jj++) {
        int j = tid + jj * 256;
        float s = 0.0f;
        for (int c = 0; c < NCLUST; c++)
            s += sWs[c] * g_cfeat[(b * NCLUST + c) * IDIM + j];
        sl[j] = s;
    }
    __syncthreads();

    float acc = bint[tid];
    for (int k = 0; k < IDIM; k++) acc += sl[k] * Wint[(size_t)k * 256 + tid];
    st2[tid] = fmaxf(acc, 0.0f);
    __syncthreads();

    red[tid] = st2[tid] * Wcls[tid * 2 + 0];
    __syncthreads();
    for (int off = 128; off > 0; off >>= 1) {
        if (tid < off) red[tid] += red[tid + off];
        __syncthreads();
    }
    if (tid == 0) out[b * 2 + 0] = red[0] + bcls[0];
    __syncthreads();

    red[tid] = st2[tid] * Wcls[tid * 2 + 1];
    __syncthreads();
    for (int off = 128; off > 0; off >>= 1) {
        if (tid < off) red[tid] += red[tid + off];
        __syncthreads();
    }
    if (tid == 0) out[b * 2 + 1] = red[0] + bcls[1];
}

// ---------------- launch ----------------
extern "C" void kernel_launch(void* const* d_in, const int* in_sizes, int n_in,
                              void* d_out, int out_size)
{
    const float* h       = (const float*)d_in[0];
    const int*   cids    = (const int*)  d_in[1];
    const float* emb     = (const float*)d_in[2];
    const float* W_fuse  = (const float*)d_in[3];
    const float* b_fuse  = (const float*)d_in[4];
    const float* Wa1     = (const float*)d_in[5];
    const float* ba1     = (const float*)d_in[6];
    const float* Wb1     = (const float*)d_in[7];
    const float* bb1     = (const float*)d_in[8];
    const float* Wc1     = (const float*)d_in[9];
    // d_in[10] = bc1 (softmax-invariant, dropped)
    const float* W_intra = (const float*)d_in[11];
    const float* b_intra = (const float*)d_in[12];
    const float* Wa2     = (const float*)d_in[13];
    const float* ba2     = (const float*)d_in[14];
    const float* Wb2     = (const float*)d_in[15];
    const float* bb2     = (const float*)d_in[16];
    const float* Wc2     = (const float*)d_in[17];
    const float* bc2     = (const float*)d_in[18];
    const float* W_inter = (const float*)d_in[19];
    const float* b_inter = (const float*)d_in[20];
    const float* W_cls   = (const float*)d_in[21];
    const float* b_cls   = (const float*)d_in[22];
    float* out = (float*)d_out;

    // unconditional (no static guard — harness rule); not a stream op, capture-safe, idempotent
    cudaFuncSetAttribute(fuse_mma_kernel,
                         cudaFuncAttributeMaxDynamicSharedMemorySize, F_DSMEM_BYTES);
    cudaFuncSetAttribute(attn1_mma_kernel,
                         cudaFuncAttributeMaxDynamicSharedMemorySize, A_DSMEM_BYTES);

    init_kernel<<<256, 256>>>();
    fuse_mma_kernel<<<dim3(IDIM / 128, MTOT / 128), 256, F_DSMEM_BYTES>>>(h, cids, emb, W_fuse, b_fuse);
    attn1_mma_kernel<<<dim3(DDIM / 64, MTOT / 128), 256, A_DSMEM_BYTES>>>(Wa1, ba1, Wb1, bb1, Wc1);
    segmax_kernel<<<256, 256>>>(cids);
    segsum_kernel<<<256, 256>>>(cids);
    cfeat_kernel<<<BATCH * 64, 256>>>(cids);
    intra_kernel<<<NSEG, 256>>>(W_intra, b_intra);
    attn2_kernel<<<NSEG, 256>>>(Wa2, ba2, Wb2, bb2, Wc2, bc2);
    final_kernel<<<BATCH, 256>>>(W_inter, b_inter, W_cls, b_cls, out);
}